// round 11
// baseline (speedup 1.0000x reference)
#include <cuda_runtime.h>

// NormmaxBisect: alpha=1.5 normmax over last dim (d=2048).
// R8: warm-start Newton -> 160.7us, DRAM 80.7%, occ 71% (regs=40, 12 blk/SM).
// R9: hybrid row placement: 12 floats in regs + 4 floats (2KB) in smem per
// thread -> 36-reg cap -> 14 blocks/SM (+17% rows in flight). Smem chunk is
// re-read per phase (short live ranges) so the reg peak stays at 36. Only
// +8KB smem traffic/block, keeping L1 well under the ~75% throttle R5 hit.
// ld.cs on X + st.cs on Y (one-pass data). Solver unchanged from R8.

#define D       2048
#define TPB     128
#define ITMAX   20

__device__ __forceinline__ float4 ldcs4(const float4* p) {
    float4 v;
    asm volatile("ld.global.cs.v4.f32 {%0,%1,%2,%3}, [%4];"
                 : "=f"(v.x), "=f"(v.y), "=f"(v.z), "=f"(v.w) : "l"(p));
    return v;
}
__device__ __forceinline__ void stcs4(float4* p, float4 v) {
    asm volatile("st.global.cs.v4.f32 [%0], {%1,%2,%3,%4};"
                 :: "l"(p), "f"(v.x), "f"(v.y), "f"(v.z), "f"(v.w) : "memory");
}

__global__ __launch_bounds__(TPB, 14)
void normmax_bisect_kernel(const float* __restrict__ X, float* __restrict__ Y) {
    __shared__ float4 s_half[TPB];      // 4th row chunk (2KB)
    __shared__ float  s_act[D];         // compacted actives (typ ~13; worst D)
    __shared__ int    s_wsum[TPB / 32];
    __shared__ float  s_wmax[TPB / 32];
    __shared__ float  s_res[2];         // {tau, 1/sum}

    const size_t row = blockIdx.x;
    const float4* xr = reinterpret_cast<const float4*>(X + row * (size_t)D);
    float4*       yr = reinterpret_cast<float4*>(Y + row * (size_t)D);
    const int tid  = threadIdx.x;
    const int lane = tid & 31;
    const int wid  = tid >> 5;

    // ---- phase 1: chunks 0-2 into regs, chunk 3 into smem; block max ----
    float4 v[3];
    float mx;
    {
        v[0] = ldcs4(xr + 0 * TPB + tid);
        v[1] = ldcs4(xr + 1 * TPB + tid);
        v[2] = ldcs4(xr + 2 * TPB + tid);
        float4 t3 = ldcs4(xr + 3 * TPB + tid);
        s_half[tid] = t3;
        mx = fmaxf(fmaxf(v[0].x, v[0].y), fmaxf(v[0].z, v[0].w));
        mx = fmaxf(mx, fmaxf(fmaxf(v[1].x, v[1].y), fmaxf(v[1].z, v[1].w)));
        mx = fmaxf(mx, fmaxf(fmaxf(v[2].x, v[2].y), fmaxf(v[2].z, v[2].w)));
        mx = fmaxf(mx, fmaxf(fmaxf(t3.x, t3.y), fmaxf(t3.z, t3.w)));
    }
#pragma unroll
    for (int o = 16; o; o >>= 1)
        mx = fmaxf(mx, __shfl_xor_sync(0xffffffffu, mx, o));
    if (lane == 0) s_wmax[wid] = mx;
    __syncthreads();                     // also publishes s_half
    mx = fmaxf(fmaxf(s_wmax[0], s_wmax[1]), fmaxf(s_wmax[2], s_wmax[3]));

    const float thresh = mx - 1.0f;  // tau >= max-1 forever => x<=max-1 dead

    // ---- phase 2: ordered compaction of actives into smem ----
    int lcnt = 0;
    {
#pragma unroll
        for (int k = 0; k < 3; k++) {
            lcnt += (v[k].x > thresh) + (v[k].y > thresh) +
                    (v[k].z > thresh) + (v[k].w > thresh);
        }
        float4 t3 = s_half[tid];         // re-read; dies before scan
        lcnt += (t3.x > thresh) + (t3.y > thresh) +
                (t3.z > thresh) + (t3.w > thresh);
    }
    int scan = lcnt;
#pragma unroll
    for (int o = 1; o < 32; o <<= 1) {
        int n = __shfl_up_sync(0xffffffffu, scan, o);
        if (lane >= o) scan += n;
    }
    if (lane == 31) s_wsum[wid] = scan;
    __syncthreads();
    int base = scan - lcnt;
#pragma unroll
    for (int w = 0; w < TPB / 32; w++)
        if (w < wid) base += s_wsum[w];
    const int cnt = s_wsum[0] + s_wsum[1] + s_wsum[2] + s_wsum[3];

    {
        int p = base;
#pragma unroll
        for (int k = 0; k < 3; k++) {
            if (v[k].x > thresh) s_act[p++] = v[k].x;
            if (v[k].y > thresh) s_act[p++] = v[k].y;
            if (v[k].z > thresh) s_act[p++] = v[k].z;
            if (v[k].w > thresh) s_act[p++] = v[k].w;
        }
        float4 t3 = s_half[tid];         // re-read; dies after writes
        if (t3.x > thresh) s_act[p++] = t3.x;
        if (t3.y > thresh) s_act[p++] = t3.y;
        if (t3.z > thresh) s_act[p++] = t3.z;
        if (t3.w > thresh) s_act[p++] = t3.w;
    }
    __syncthreads();

    // ---- phase 3: warm-started Newton on one warp (rotates across SMSPs) --
    // f(tau) = sum(max(x-tau,0)^3) - 1: convex, decreasing.
    // tau_b = max - cnt^(-1/3) >= tau*  (cnt*t_max^3 >= sum t^3 = 1), so
    // f(tau_b) <= 0; Newton from the right lands left of the root, then
    // converges monotonically. Early exit: |f3-1| < 2e-6 (f2 >= 1 provably).
    if (wid == (int)(blockIdx.x & 3)) {
        float t0  = __expf(-0.33333333f * __logf((float)cnt));
        float tau = mx - t0;
        const float tlo = mx - 1.0f;

        float f2, f3;
        if (cnt <= 32) {                       // common case (~13 actives)
            float a = (lane < cnt) ? s_act[lane] : -3.402823466e38f;
            int it = 0;
#pragma unroll 1
            for (;;) {
                float t  = fmaxf(a - tau, 0.f);
                float t2 = t * t;
                f2 = t2;
                f3 = t2 * t;
#pragma unroll
                for (int o = 16; o; o >>= 1) {  // dual butterfly, pipelined
                    f3 += __shfl_xor_sync(0xffffffffu, f3, o);
                    f2 += __shfl_xor_sync(0xffffffffu, f2, o);
                }
                if (fabsf(f3 - 1.0f) < 2e-6f || ++it >= ITMAX) break;
                tau = fmaxf(tau + (f3 - 1.0f) / (3.0f * f2), tlo);
            }
            if (lane == 0) { s_res[0] = tau; s_res[1] = 1.0f / f2; }
        } else {                               // rare: stride smem actives
            int it = 0;
#pragma unroll 1
            for (;;) {
                f2 = 0.f; f3 = 0.f;
                for (int i = lane; i < cnt; i += 32) {
                    float t  = fmaxf(s_act[i] - tau, 0.f);
                    float t2 = t * t;
                    f2 += t2;
                    f3 = fmaf(t2, t, f3);
                }
#pragma unroll
                for (int o = 16; o; o >>= 1) {
                    f3 += __shfl_xor_sync(0xffffffffu, f3, o);
                    f2 += __shfl_xor_sync(0xffffffffu, f2, o);
                }
                if (fabsf(f3 - 1.0f) < 2e-6f || ++it >= ITMAX + 8) break;
                tau = fmaxf(tau + (f3 - 1.0f) / (3.0f * f2), tlo);
            }
            if (lane == 0) { s_res[0] = tau; s_res[1] = 1.0f / f2; }
        }
    }
    __syncthreads();

    // ---- phase 4: emit normalized p (streaming stores) ----
    const float tau = s_res[0];
    const float inv = s_res[1];
#pragma unroll
    for (int k = 0; k < 3; k++) {
        float4 o;
        float u;
        u = fmaxf(v[k].x - tau, 0.f); o.x = u * u * inv;
        u = fmaxf(v[k].y - tau, 0.f); o.y = u * u * inv;
        u = fmaxf(v[k].z - tau, 0.f); o.z = u * u * inv;
        u = fmaxf(v[k].w - tau, 0.f); o.w = u * u * inv;
        stcs4(yr + k * TPB + tid, o);
    }
    {
        float4 t3 = s_half[tid];
        float4 o;
        float u;
        u = fmaxf(t3.x - tau, 0.f); o.x = u * u * inv;
        u = fmaxf(t3.y - tau, 0.f); o.y = u * u * inv;
        u = fmaxf(t3.z - tau, 0.f); o.z = u * u * inv;
        u = fmaxf(t3.w - tau, 0.f); o.w = u * u * inv;
        stcs4(yr + 3 * TPB + tid, o);
    }
}

extern "C" void kernel_launch(void* const* d_in, const int* in_sizes, int n_in,
                              void* d_out, int out_size) {
    const float* X = (const float*)d_in[0];
    float*       Y = (float*)d_out;
    const int rows = in_sizes[0] / D;   // 65536
    normmax_bisect_kernel<<<rows, TPB>>>(X, Y);
}